// round 15
// baseline (speedup 1.0000x reference)
#include <cuda_runtime.h>
#include <cuda_fp16.h>
#include <cstdint>
#include <math.h>

// Problem constants: B=4096, IN_F=2048, OUT_F=8192, NG=16
#define M_DIM   4096
#define K_DIM   2048
#define N_DIM   8192
#define NGROUPS 16
#define GSIZE   (N_DIM / NGROUPS)   // 512
#define EPS     1e-5f

// GEMM tiling: CTA 128x128, 8 warps of 32x64 (4M x 2N), 256 threads
#define BM 128
#define BN 128
#define CHUNK 64                    // K elems per chunk = 128 B rows (fp16)
#define NCHUNK (K_DIM / CHUNK)      // 32
#define A_ST (BM * 128)             // 16 KB
#define B_ST (BN * 128)             // 16 KB
#define STG  (A_ST + B_ST)          // 32 KB
#define NSTAGE 3
#define SMEM_GEMM (NSTAGE * STG)    // 98304 -> 2 CTAs/SM

#define SWZ(o) ((o) ^ ((((uint32_t)(o)) >> 3) & 0x70))

// -------- scratch: fp16 copies of x and W --------------------------------
__device__ __half g_x16[(size_t)M_DIM * K_DIM];     // 16 MB
__device__ __half g_w16[(size_t)N_DIM * K_DIM];     // 32 MB

// -------- PTX helpers (plain sm_80 PTX) ----------------------------------
__device__ __forceinline__ uint32_t smem_u32(const void* p) {
    uint32_t a;
    asm("{ .reg .u64 t; cvta.to.shared.u64 t, %1; cvt.u32.u64 %0, t; }" : "=r"(a) : "l"(p));
    return a;
}
#define CP_ASYNC16(dst, src) \
    asm volatile("cp.async.cg.shared.global [%0], [%1], 16;" :: "r"(dst), "l"(src) : "memory")
#define CP_COMMIT() asm volatile("cp.async.commit_group;" ::: "memory")
#define CP_WAIT(n)  asm volatile("cp.async.wait_group %0;" :: "n"(n) : "memory")

#define LDSM_X4(r0, r1, r2, r3, addr) \
    asm volatile("ldmatrix.sync.aligned.m8n8.x4.shared.b16 {%0,%1,%2,%3}, [%4];" \
        : "=r"(r0), "=r"(r1), "=r"(r2), "=r"(r3) : "r"(addr))

#define MMA16816F16(d, a, b0v, b1v) \
    asm volatile("mma.sync.aligned.m16n8k16.row.col.f32.f16.f16.f32 " \
        "{%0,%1,%2,%3}, {%4,%5,%6,%7}, {%8,%9}, {%0,%1,%2,%3};" \
        : "+f"((d)[0]), "+f"((d)[1]), "+f"((d)[2]), "+f"((d)[3]) \
        : "r"((a)[0]), "r"((a)[1]), "r"((a)[2]), "r"((a)[3]), "r"(b0v), "r"(b1v))

// -------- convert: fp32 -> fp16, both tensors in ONE launch --------------
// Sources are touch-once -> streaming loads. Outputs stay default policy
// (re-read many times by the GEMM; 48 MB fits L2).
__global__ __launch_bounds__(256)
void cvt_both_kernel(const float* __restrict__ x, __half* __restrict__ x16,
                     const float* __restrict__ W, __half* __restrict__ w16,
                     int n8x, int n8tot)
{
    int i = blockIdx.x * 256 + threadIdx.x;
    if (i >= n8tot) return;
    const float* src;
    __half* dst;
    int idx;
    if (i < n8x) { src = x; dst = x16; idx = i; }
    else         { src = W; dst = w16; idx = i - n8x; }

    const float4 v0 = __ldcs(&reinterpret_cast<const float4*>(src)[idx * 2]);
    const float4 v1 = __ldcs(&reinterpret_cast<const float4*>(src)[idx * 2 + 1]);
    __half2 h0 = __floats2half2_rn(v0.x, v0.y);
    __half2 h1 = __floats2half2_rn(v0.z, v0.w);
    __half2 h2 = __floats2half2_rn(v1.x, v1.y);
    __half2 h3 = __floats2half2_rn(v1.z, v1.w);
    uint4 u;
    u.x = *reinterpret_cast<uint32_t*>(&h0);
    u.y = *reinterpret_cast<uint32_t*>(&h1);
    u.z = *reinterpret_cast<uint32_t*>(&h2);
    u.w = *reinterpret_cast<uint32_t*>(&h3);
    reinterpret_cast<uint4*>(dst)[idx] = u;
}

// -------- GEMM: C = x16 @ W16^T + bias (fp16 in, fp32 accum/out) ---------
// EXACT R11/R14 structure: 8 warps of 32x64, 3-stage ring, prefetch at loop
// bottom, unconditional CP_COMMIT (race fix), fp32 float2 epilogue.
__global__ __launch_bounds__(256, 2)
void gemm_f16_kernel(const float* __restrict__ bias, float* __restrict__ C)
{
    extern __shared__ __align__(128) char sm[];
    const uint32_t smem_base = smem_u32(sm);
    const int tid = threadIdx.x, wid = tid >> 5, lane = tid & 31;
    const int wm = wid & 3, wn = wid >> 2;           // 4M x 2N warps, 32x64 each
    const int mrow0 = blockIdx.x * BM;
    const int nrow0 = blockIdx.y * BN;

    float acc[2][8][4];
#pragma unroll
    for (int i = 0; i < 2; i++)
#pragma unroll
        for (int j = 0; j < 8; j++)
#pragma unroll
            for (int r = 0; r < 4; r++) acc[i][j][r] = 0.0f;

    auto prefetch = [&](int c) {
        const uint32_t base = smem_base + (c % NSTAGE) * STG;
        const int k0 = c * CHUNK;
#pragma unroll
        for (int i = 0; i < 4; i++) {
            int idx = tid + i * 256; int r = idx >> 3, u = idx & 7;
            CP_ASYNC16(base + SWZ(r * 128 + u * 16),
                       &g_x16[(size_t)(mrow0 + r) * K_DIM + k0 + u * 8]);
        }
#pragma unroll
        for (int i = 0; i < 4; i++) {
            int idx = tid + i * 256; int r = idx >> 3, u = idx & 7;
            CP_ASYNC16(base + A_ST + SWZ(r * 128 + u * 16),
                       &g_w16[(size_t)(nrow0 + r) * K_DIM + k0 + u * 8]);
        }
    };

    prefetch(0); CP_COMMIT();
    prefetch(1); CP_COMMIT();

    const int a_row = wm * 32 + (lane & 15);
    const int a_kb  = (lane >> 4) * 16;
    const int b_row = wn * 64 + (lane & 7) + ((lane >> 4) << 3);
    const int b_kb  = ((lane >> 3) & 1) * 16;

    for (int c = 0; c < NCHUNK; ++c) {
        // Exactly 2 groups outstanding here (stage c, stage c+1/empty):
        // CP_WAIT(1) retires stage c's group -> its data is complete.
        // By this barrier every warp finished reading stage c-1, so the
        // prefetch(c+2) below into buffer (c+2)%3 == (c-1)%3 is safe.
        CP_WAIT(1);
        __syncthreads();

        const uint32_t aB = smem_base + (c % NSTAGE) * STG;
        const uint32_t bB = aB + A_ST;
#pragma unroll
        for (int ks = 0; ks < 4; ++ks) {
            uint32_t a[2][4], b[4][4];
#pragma unroll
            for (int i = 0; i < 2; i++)
                LDSM_X4(a[i][0], a[i][1], a[i][2], a[i][3],
                        aB + SWZ((a_row + i * 16) * 128 + ks * 32 + a_kb));
#pragma unroll
            for (int j = 0; j < 4; j++)
                LDSM_X4(b[j][0], b[j][1], b[j][2], b[j][3],
                        bB + SWZ((b_row + j * 16) * 128 + ks * 32 + b_kb));
#pragma unroll
            for (int i = 0; i < 2; i++)
#pragma unroll
                for (int j = 0; j < 4; j++) {
                    MMA16816F16(acc[i][2 * j + 0], a[i], b[j][0], b[j][1]);
                    MMA16816F16(acc[i][2 * j + 1], a[i], b[j][2], b[j][3]);
                }
        }

        if (c + 2 < NCHUNK) prefetch(c + 2);
        CP_COMMIT();   // unconditional: empty group when no prefetch
    }

    const int m_base = mrow0 + wm * 32 + (lane >> 2);
    const int n_base = nrow0 + wn * 64 + (lane & 3) * 2;
#pragma unroll
    for (int i = 0; i < 2; i++) {
#pragma unroll
        for (int j = 0; j < 8; j++) {
            int n0 = n_base + j * 8;
            float b0 = bias[n0], b1 = bias[n0 + 1];
            int m0 = m_base + i * 16;
            float2 lo2 = {acc[i][j][0] + b0, acc[i][j][1] + b1};
            float2 hi2 = {acc[i][j][2] + b0, acc[i][j][3] + b1};
            *reinterpret_cast<float2*>(C + (size_t)m0 * N_DIM + n0)       = lo2;
            *reinterpret_cast<float2*>(C + (size_t)(m0 + 8) * N_DIM + n0) = hi2;
        }
    }
}

// -------- GroupNorm + SiLU + mult + SiLU, 4 rows per block ---------------
// warp w -> group w for rows 4*blk .. 4*blk+3. 16 independent LDG.128 per
// lane in flight before the reductions (MLP up from 8), 4 parallel
// reduce/MUFU chains. Streaming loads/stores (touch-once data).
__device__ __forceinline__ float fast_sigmoid(float x) {
    float e = __expf(-x);
    return __fdividef(1.0f, 1.0f + e);
}

__global__ __launch_bounds__(512)
void gn_silu_kernel(float* __restrict__ y,
                    const float* __restrict__ gn_w,
                    const float* __restrict__ gn_b,
                    const float* __restrict__ mult_w)
{
    const int row0 = blockIdx.x * 4;
    const int w    = threadIdx.x >> 5;
    const int lane = threadIdx.x & 31;

    float4* p[4];
#pragma unroll
    for (int r = 0; r < 4; r++)
        p[r] = reinterpret_cast<float4*>(y + (size_t)(row0 + r) * N_DIM + w * GSIZE);

    float4 v[4][4];
#pragma unroll
    for (int t = 0; t < 4; t++)
#pragma unroll
        for (int r = 0; r < 4; r++)
            v[r][t] = __ldcs(&p[r][lane + t * 32]);

    float s[4] = {0, 0, 0, 0}, ss[4] = {0, 0, 0, 0};
#pragma unroll
    for (int r = 0; r < 4; r++)
#pragma unroll
        for (int t = 0; t < 4; t++) {
            s[r]  += v[r][t].x + v[r][t].y + v[r][t].z + v[r][t].w;
            ss[r] += v[r][t].x*v[r][t].x + v[r][t].y*v[r][t].y
                   + v[r][t].z*v[r][t].z + v[r][t].w*v[r][t].w;
        }
#pragma unroll
    for (int o = 16; o > 0; o >>= 1) {
#pragma unroll
        for (int r = 0; r < 4; r++) {
            s[r]  += __shfl_xor_sync(0xffffffffu, s[r],  o);
            ss[r] += __shfl_xor_sync(0xffffffffu, ss[r], o);
        }
    }
    const float inv_n = 1.0f / (float)GSIZE;
    float mean[4], rstd[4];
#pragma unroll
    for (int r = 0; r < 4; r++) {
        mean[r] = s[r] * inv_n;
        rstd[r] = rsqrtf(fmaxf(ss[r] * inv_n - mean[r] * mean[r], 0.0f) + EPS);
    }

#pragma unroll
    for (int t = 0; t < 4; t++) {
        const int c0 = w * GSIZE + (lane + t * 32) * 4;
        float gw[4], gb[4], mw[4];
#pragma unroll
        for (int j = 0; j < 4; j++) {
            gw[j] = __ldg(&gn_w[c0 + j]);
            gb[j] = __ldg(&gn_b[c0 + j]);
            mw[j] = __ldg(&mult_w[c0 + j]);
        }
#pragma unroll
        for (int r = 0; r < 4; r++) {
            float a[4] = {v[r][t].x, v[r][t].y, v[r][t].z, v[r][t].w};
            float o[4];
#pragma unroll
            for (int j = 0; j < 4; j++) {
                float n  = (a[j] - mean[r]) * rstd[r] * gw[j] + gb[j];
                float t1 = n * fast_sigmoid(n) * mw[j];
                o[j] = t1 * fast_sigmoid(t1);
            }
            float4 ov = {o[0], o[1], o[2], o[3]};
            __stcs(&p[r][lane + t * 32], ov);
        }
    }
}

// -------------------------------------------------------------------------
extern "C" void kernel_launch(void* const* d_in, const int* in_sizes, int n_in,
                              void* d_out, int out_size)
{
    const float* x      = (const float*)d_in[0];
    const float* W      = (const float*)d_in[1];
    const float* b      = (const float*)d_in[2];
    const float* gn_w   = (const float*)d_in[3];
    const float* gn_b   = (const float*)d_in[4];
    const float* mult_w = (const float*)d_in[5];
    float* out = (float*)d_out;

    __half *x16, *w16;
    cudaGetSymbolAddress((void**)&x16, g_x16);
    cudaGetSymbolAddress((void**)&w16, g_w16);

    int n8x   = (M_DIM * K_DIM) / 8;
    int n8tot = n8x + (N_DIM * K_DIM) / 8;
    cvt_both_kernel<<<(n8tot + 255) / 256, 256>>>(x, x16, W, w16, n8x, n8tot);

    cudaFuncSetAttribute(gemm_f16_kernel,
                         cudaFuncAttributeMaxDynamicSharedMemorySize, SMEM_GEMM);

    dim3 ggrid(M_DIM / BM, N_DIM / BN);   // (32, 64)
    gemm_f16_kernel<<<ggrid, 256, SMEM_GEMM>>>(b, out);

    gn_silu_kernel<<<M_DIM / 4, 512>>>(out, gn_w, gn_b, mult_w);
}

// round 16
// speedup vs baseline: 1.0153x; 1.0153x over previous
#include <cuda_runtime.h>
#include <cuda_fp16.h>
#include <cstdint>
#include <math.h>

// Problem constants: B=4096, IN_F=2048, OUT_F=8192, NG=16
#define M_DIM   4096
#define K_DIM   2048
#define N_DIM   8192
#define NGROUPS 16
#define GSIZE   (N_DIM / NGROUPS)   // 512
#define EPS     1e-5f

// GEMM tiling: CTA 128x128, 8 warps of 32x64 (4M x 2N), 256 threads
#define BM 128
#define BN 128
#define CHUNK 64                    // K elems per chunk = 128 B rows (fp16)
#define NCHUNK (K_DIM / CHUNK)      // 32
#define A_ST (BM * 128)             // 16 KB
#define B_ST (BN * 128)             // 16 KB
#define STG  (A_ST + B_ST)          // 32 KB
#define NSTAGE 3
#define SMEM_GEMM (NSTAGE * STG)    // 98304 -> 2 CTAs/SM

#define SWZ(o) ((o) ^ ((((uint32_t)(o)) >> 3) & 0x70))

// -------- scratch: fp16 copies of x and W --------------------------------
__device__ __half g_x16[(size_t)M_DIM * K_DIM];     // 16 MB
__device__ __half g_w16[(size_t)N_DIM * K_DIM];     // 32 MB

// -------- PTX helpers (plain sm_80 PTX) ----------------------------------
__device__ __forceinline__ uint32_t smem_u32(const void* p) {
    uint32_t a;
    asm("{ .reg .u64 t; cvta.to.shared.u64 t, %1; cvt.u32.u64 %0, t; }" : "=r"(a) : "l"(p));
    return a;
}
#define CP_ASYNC16(dst, src) \
    asm volatile("cp.async.cg.shared.global [%0], [%1], 16;" :: "r"(dst), "l"(src) : "memory")
#define CP_COMMIT() asm volatile("cp.async.commit_group;" ::: "memory")
#define CP_WAIT(n)  asm volatile("cp.async.wait_group %0;" :: "n"(n) : "memory")

#define LDSM_X4(r0, r1, r2, r3, addr) \
    asm volatile("ldmatrix.sync.aligned.m8n8.x4.shared.b16 {%0,%1,%2,%3}, [%4];" \
        : "=r"(r0), "=r"(r1), "=r"(r2), "=r"(r3) : "r"(addr))

#define MMA16816F16(d, a, b0v, b1v) \
    asm volatile("mma.sync.aligned.m16n8k16.row.col.f32.f16.f16.f32 " \
        "{%0,%1,%2,%3}, {%4,%5,%6,%7}, {%8,%9}, {%0,%1,%2,%3};" \
        : "+f"((d)[0]), "+f"((d)[1]), "+f"((d)[2]), "+f"((d)[3]) \
        : "r"((a)[0]), "r"((a)[1]), "r"((a)[2]), "r"((a)[3]), "r"(b0v), "r"(b1v))

// -------- convert: fp32 -> fp16, both tensors in ONE launch --------------
// Sources are touch-once -> streaming loads (measured win in R15). Outputs
// stay default policy (re-read many times by the GEMM; 48 MB fits L2).
__global__ __launch_bounds__(256)
void cvt_both_kernel(const float* __restrict__ x, __half* __restrict__ x16,
                     const float* __restrict__ W, __half* __restrict__ w16,
                     int n8x, int n8tot)
{
    int i = blockIdx.x * 256 + threadIdx.x;
    if (i >= n8tot) return;
    const float* src;
    __half* dst;
    int idx;
    if (i < n8x) { src = x; dst = x16; idx = i; }
    else         { src = W; dst = w16; idx = i - n8x; }

    const float4 v0 = __ldcs(&reinterpret_cast<const float4*>(src)[idx * 2]);
    const float4 v1 = __ldcs(&reinterpret_cast<const float4*>(src)[idx * 2 + 1]);
    __half2 h0 = __floats2half2_rn(v0.x, v0.y);
    __half2 h1 = __floats2half2_rn(v0.z, v0.w);
    __half2 h2 = __floats2half2_rn(v1.x, v1.y);
    __half2 h3 = __floats2half2_rn(v1.z, v1.w);
    uint4 u;
    u.x = *reinterpret_cast<uint32_t*>(&h0);
    u.y = *reinterpret_cast<uint32_t*>(&h1);
    u.z = *reinterpret_cast<uint32_t*>(&h2);
    u.w = *reinterpret_cast<uint32_t*>(&h3);
    reinterpret_cast<uint4*>(dst)[idx] = u;
}

// -------- GEMM: C = x16 @ W16^T + bias (fp16 in, fp32 accum/out) ---------
// EXACT R11/R14 structure: 8 warps of 32x64, 3-stage ring, prefetch at loop
// bottom, unconditional CP_COMMIT (race fix), fp32 float2 epilogue.
__global__ __launch_bounds__(256, 2)
void gemm_f16_kernel(const float* __restrict__ bias, float* __restrict__ C)
{
    extern __shared__ __align__(128) char sm[];
    const uint32_t smem_base = smem_u32(sm);
    const int tid = threadIdx.x, wid = tid >> 5, lane = tid & 31;
    const int wm = wid & 3, wn = wid >> 2;           // 4M x 2N warps, 32x64 each
    const int mrow0 = blockIdx.x * BM;
    const int nrow0 = blockIdx.y * BN;

    float acc[2][8][4];
#pragma unroll
    for (int i = 0; i < 2; i++)
#pragma unroll
        for (int j = 0; j < 8; j++)
#pragma unroll
            for (int r = 0; r < 4; r++) acc[i][j][r] = 0.0f;

    auto prefetch = [&](int c) {
        const uint32_t base = smem_base + (c % NSTAGE) * STG;
        const int k0 = c * CHUNK;
#pragma unroll
        for (int i = 0; i < 4; i++) {
            int idx = tid + i * 256; int r = idx >> 3, u = idx & 7;
            CP_ASYNC16(base + SWZ(r * 128 + u * 16),
                       &g_x16[(size_t)(mrow0 + r) * K_DIM + k0 + u * 8]);
        }
#pragma unroll
        for (int i = 0; i < 4; i++) {
            int idx = tid + i * 256; int r = idx >> 3, u = idx & 7;
            CP_ASYNC16(base + A_ST + SWZ(r * 128 + u * 16),
                       &g_w16[(size_t)(nrow0 + r) * K_DIM + k0 + u * 8]);
        }
    };

    prefetch(0); CP_COMMIT();
    prefetch(1); CP_COMMIT();

    const int a_row = wm * 32 + (lane & 15);
    const int a_kb  = (lane >> 4) * 16;
    const int b_row = wn * 64 + (lane & 7) + ((lane >> 4) << 3);
    const int b_kb  = ((lane >> 3) & 1) * 16;

    for (int c = 0; c < NCHUNK; ++c) {
        // Exactly 2 groups outstanding here (stage c, stage c+1/empty):
        // CP_WAIT(1) retires stage c's group -> its data is complete.
        // By this barrier every warp finished reading stage c-1, so the
        // prefetch(c+2) below into buffer (c+2)%3 == (c-1)%3 is safe.
        CP_WAIT(1);
        __syncthreads();

        const uint32_t aB = smem_base + (c % NSTAGE) * STG;
        const uint32_t bB = aB + A_ST;
#pragma unroll
        for (int ks = 0; ks < 4; ++ks) {
            uint32_t a[2][4], b[4][4];
#pragma unroll
            for (int i = 0; i < 2; i++)
                LDSM_X4(a[i][0], a[i][1], a[i][2], a[i][3],
                        aB + SWZ((a_row + i * 16) * 128 + ks * 32 + a_kb));
#pragma unroll
            for (int j = 0; j < 4; j++)
                LDSM_X4(b[j][0], b[j][1], b[j][2], b[j][3],
                        bB + SWZ((b_row + j * 16) * 128 + ks * 32 + b_kb));
#pragma unroll
            for (int i = 0; i < 2; i++)
#pragma unroll
                for (int j = 0; j < 4; j++) {
                    MMA16816F16(acc[i][2 * j + 0], a[i], b[j][0], b[j][1]);
                    MMA16816F16(acc[i][2 * j + 1], a[i], b[j][2], b[j][3]);
                }
        }

        if (c + 2 < NCHUNK) prefetch(c + 2);
        CP_COMMIT();   // unconditional: empty group when no prefetch
    }

    const int m_base = mrow0 + wm * 32 + (lane >> 2);
    const int n_base = nrow0 + wn * 64 + (lane & 3) * 2;
#pragma unroll
    for (int i = 0; i < 2; i++) {
#pragma unroll
        for (int j = 0; j < 8; j++) {
            int n0 = n_base + j * 8;
            float b0 = bias[n0], b1 = bias[n0 + 1];
            int m0 = m_base + i * 16;
            float2 lo2 = {acc[i][j][0] + b0, acc[i][j][1] + b1};
            float2 hi2 = {acc[i][j][2] + b0, acc[i][j][3] + b1};
            *reinterpret_cast<float2*>(C + (size_t)m0 * N_DIM + n0)       = lo2;
            *reinterpret_cast<float2*>(C + (size_t)(m0 + 8) * N_DIM + n0) = hi2;
        }
    }
}

// -------- GroupNorm + SiLU + mult + SiLU, 2 rows per block ---------------
// R14's measured-best shape: warp w -> group w of rows 2*blk, 2*blk+1,
// interleaved independent chains, streaming loads/stores, __ldg params.
__device__ __forceinline__ float fast_sigmoid(float x) {
    float e = __expf(-x);
    return __fdividef(1.0f, 1.0f + e);
}

__global__ __launch_bounds__(512)
void gn_silu_kernel(float* __restrict__ y,
                    const float* __restrict__ gn_w,
                    const float* __restrict__ gn_b,
                    const float* __restrict__ mult_w)
{
    const int row0 = blockIdx.x * 2;
    const int w    = threadIdx.x >> 5;
    const int lane = threadIdx.x & 31;

    float4* p0 = reinterpret_cast<float4*>(y + (size_t)row0 * N_DIM + w * GSIZE);
    float4* p1 = reinterpret_cast<float4*>(y + (size_t)(row0 + 1) * N_DIM + w * GSIZE);

    float4 v0[4], v1[4];
#pragma unroll
    for (int t = 0; t < 4; t++) {
        v0[t] = __ldcs(&p0[lane + t * 32]);
        v1[t] = __ldcs(&p1[lane + t * 32]);
    }

    float s0 = 0.0f, ss0 = 0.0f, s1 = 0.0f, ss1 = 0.0f;
#pragma unroll
    for (int t = 0; t < 4; t++) {
        s0  += v0[t].x + v0[t].y + v0[t].z + v0[t].w;
        ss0 += v0[t].x*v0[t].x + v0[t].y*v0[t].y + v0[t].z*v0[t].z + v0[t].w*v0[t].w;
        s1  += v1[t].x + v1[t].y + v1[t].z + v1[t].w;
        ss1 += v1[t].x*v1[t].x + v1[t].y*v1[t].y + v1[t].z*v1[t].z + v1[t].w*v1[t].w;
    }
#pragma unroll
    for (int o = 16; o > 0; o >>= 1) {
        s0  += __shfl_xor_sync(0xffffffffu, s0,  o);
        s1  += __shfl_xor_sync(0xffffffffu, s1,  o);
        ss0 += __shfl_xor_sync(0xffffffffu, ss0, o);
        ss1 += __shfl_xor_sync(0xffffffffu, ss1, o);
    }
    const float inv_n = 1.0f / (float)GSIZE;
    const float mean0 = s0 * inv_n;
    const float mean1 = s1 * inv_n;
    const float rstd0 = rsqrtf(fmaxf(ss0 * inv_n - mean0 * mean0, 0.0f) + EPS);
    const float rstd1 = rsqrtf(fmaxf(ss1 * inv_n - mean1 * mean1, 0.0f) + EPS);

#pragma unroll
    for (int t = 0; t < 4; t++) {
        float a0[4] = {v0[t].x, v0[t].y, v0[t].z, v0[t].w};
        float a1[4] = {v1[t].x, v1[t].y, v1[t].z, v1[t].w};
        float o0[4], o1[4];
        const int c0 = w * GSIZE + (lane + t * 32) * 4;
#pragma unroll
        for (int j = 0; j < 4; j++) {
            int c = c0 + j;
            float gw = __ldg(&gn_w[c]), gb = __ldg(&gn_b[c]), mw = __ldg(&mult_w[c]);
            float n0 = (a0[j] - mean0) * rstd0 * gw + gb;
            float n1 = (a1[j] - mean1) * rstd1 * gw + gb;
            float t0 = n0 * fast_sigmoid(n0) * mw;
            float t1 = n1 * fast_sigmoid(n1) * mw;
            o0[j] = t0 * fast_sigmoid(t0);
            o1[j] = t1 * fast_sigmoid(t1);
        }
        float4 w0 = {o0[0], o0[1], o0[2], o0[3]};
        float4 w1 = {o1[0], o1[1], o1[2], o1[3]};
        __stcs(&p0[lane + t * 32], w0);
        __stcs(&p1[lane + t * 32], w1);
    }
}

// -------------------------------------------------------------------------
extern "C" void kernel_launch(void* const* d_in, const int* in_sizes, int n_in,
                              void* d_out, int out_size)
{
    const float* x      = (const float*)d_in[0];
    const float* W      = (const float*)d_in[1];
    const float* b      = (const float*)d_in[2];
    const float* gn_w   = (const float*)d_in[3];
    const float* gn_b   = (const float*)d_in[4];
    const float* mult_w = (const float*)d_in[5];
    float* out = (float*)d_out;

    __half *x16, *w16;
    cudaGetSymbolAddress((void**)&x16, g_x16);
    cudaGetSymbolAddress((void**)&w16, g_w16);

    int n8x   = (M_DIM * K_DIM) / 8;
    int n8tot = n8x + (N_DIM * K_DIM) / 8;
    cvt_both_kernel<<<(n8tot + 255) / 256, 256>>>(x, x16, W, w16, n8x, n8tot);

    cudaFuncSetAttribute(gemm_f16_kernel,
                         cudaFuncAttributeMaxDynamicSharedMemorySize, SMEM_GEMM);

    dim3 ggrid(M_DIM / BM, N_DIM / BN);   // (32, 64)
    gemm_f16_kernel<<<ggrid, 256, SMEM_GEMM>>>(b, out);

    gn_silu_kernel<<<M_DIM / 2, 512>>>(out, gn_w, gn_b, mult_w);
}